// round 5
// baseline (speedup 1.0000x reference)
#include <cuda_runtime.h>
#include <cstdint>
#include <cstddef>

#define B_    16
#define N_    1024
#define D_    256
#define K_    16
#define S_    512
#define M_TOT (B_*N_)          /* 16384 */
#define KS_   (K_*S_)          /* 8192  */
#define ZQ_SIZE   (M_TOT*D_)   /* 4194304 */
#define PROB_SIZE ((size_t)M_TOT*S_) /* 8388608 */

// ---------------- scratch (static device globals; no runtime allocation) ----
__device__ float g_scratch[(size_t)M_TOT * KS_];   // 512 MB: logit_all, then W in-place
__device__ float g_z2[M_TOT];
__device__ float g_b2[KS_];
__device__ float g_cprobs[B_ * K_];
__device__ float g_prec[2];                        // [0]=precision_q, [1]=precision_q_cls

// ---------------- threefry2x32-20 (JAX-compatible) --------------------------
__device__ __forceinline__ void d_tf(uint32_t k0, uint32_t k1,
                                     uint32_t x0, uint32_t x1,
                                     uint32_t& o0, uint32_t& o1) {
    uint32_t ks2 = k0 ^ k1 ^ 0x1BD11BDAu;
    x0 += k0; x1 += k1;
#define TFR(r) { x0 += x1; x1 = __funnelshift_l(x1, x1, r); x1 ^= x0; }
    TFR(13) TFR(15) TFR(26) TFR(6)   x0 += k1;  x1 += ks2 + 1u;
    TFR(17) TFR(29) TFR(16) TFR(24)  x0 += ks2; x1 += k0  + 2u;
    TFR(13) TFR(15) TFR(26) TFR(6)   x0 += k0;  x1 += k1  + 3u;
    TFR(17) TFR(29) TFR(16) TFR(24)  x0 += k1;  x1 += ks2 + 4u;
    TFR(13) TFR(15) TFR(26) TFR(6)   x0 += ks2; x1 += k0  + 5u;
#undef TFR
    o0 = x0; o1 = x1;
}

// partitionable random_bits(32) for flat index i (< 2^32):
// JAX: bits1, bits2 = threefry2x32(key, hi32(i), lo32(i)); return bits1 ^ bits2
__device__ __forceinline__ uint32_t d_bits32(uint32_t k0, uint32_t k1, uint32_t i) {
    uint32_t o0, o1;
    d_tf(k0, k1, 0u, i, o0, o1);
    return o0 ^ o1;
}

__device__ __forceinline__ float bits_to_unit(uint32_t b) {
    // JAX uniform: bitcast(bits>>9 | 0x3f800000) - 1, then max(0, .)
    return fmaxf(0.0f, __uint_as_float((b >> 9) | 0x3f800000u) - 1.0f);
}

__device__ __forceinline__ float gumbel_of(float u) {
    return -logf(-logf(u + 1e-10f) + 1e-10f);
}

// ---------------- tiny kernels ----------------------------------------------
__global__ void k_scalars(const float* __restrict__ lpq,
                          const float* __restrict__ lpqc,
                          float* __restrict__ out_scalar) {
    float pq   = 1.0f + expf(lpq[0]);
    float prec = 0.5f / fmaxf(pq, 1e-10f);
    float pqc  = 1.0f + expf(lpqc[0]);
    float precc= 0.5f / fmaxf(pqc, 1e-10f);
    g_prec[0] = prec;
    g_prec[1] = precc;
    out_scalar[0] = prec;
}

__global__ void k_cprobs(const float* __restrict__ c_logits,
                         uint32_t k0, uint32_t k1) {
    __shared__ float lg[256];
    int t = threadIdx.x;
    float u = bits_to_unit(d_bits32(k0, k1, (uint32_t)t));
    float pqc = g_prec[1];
    lg[t] = (c_logits[t] * pqc + gumbel_of(u)) * 2.0f;   // /TEMP, TEMP=0.5
    __syncthreads();
    if (t < 16) {
        float mx = -1e30f;
        for (int j = 0; j < 16; j++) mx = fmaxf(mx, lg[t * 16 + j]);
        float e[16], sm = 0.0f;
        for (int j = 0; j < 16; j++) { e[j] = expf(lg[t * 16 + j] - mx); sm += e[j]; }
        for (int j = 0; j < 16; j++) g_cprobs[t * 16 + j] = e[j] / sm;
    }
}

__global__ void k_norms(const float* __restrict__ ze,
                        const float* __restrict__ books) {
    int warps = (gridDim.x * blockDim.x) >> 5;
    int w     = (blockIdx.x * blockDim.x + threadIdx.x) >> 5;
    int lane  = threadIdx.x & 31;
    for (int r = w; r < M_TOT + KS_; r += warps) {
        const float4* p = (r < M_TOT)
            ? (const float4*)(ze + (size_t)r * D_)
            : (const float4*)(books + (size_t)(r - M_TOT) * D_);
        float s = 0.0f;
#pragma unroll
        for (int j = 0; j < 2; j++) {
            float4 v = p[lane + j * 32];
            s += v.x * v.x + v.y * v.y + v.z * v.z + v.w * v.w;
        }
#pragma unroll
        for (int o = 16; o; o >>= 1) s += __shfl_xor_sync(0xffffffffu, s, o);
        if (lane == 0) { if (r < M_TOT) g_z2[r] = s; else g_b2[r - M_TOT] = s; }
    }
}

// ---------------- GEMM1: logit_all = (2*ze.booksT - z2 - b2)*prec -----------
__global__ __launch_bounds__(256)
void k_gemm1(const float* __restrict__ A, const float* __restrict__ Bm) {
    __shared__ float As[16][132];
    __shared__ float Bs[16][132];
    int t  = threadIdx.x;
    int m0 = blockIdx.y * 128, n0 = blockIdx.x * 128;
    int tx = t & 15, ty = t >> 4;
    float acc[8][8] = {};
    for (int k0 = 0; k0 < D_; k0 += 16) {
#pragma unroll
        for (int rep = 0; rep < 2; rep++) {
            int lin = rep * 256 + t;
            int row = lin >> 2;
            int c4  = (lin & 3) << 2;
            float4 va = *(const float4*)(A  + (size_t)(m0 + row) * D_ + k0 + c4);
            As[c4 + 0][row] = va.x; As[c4 + 1][row] = va.y;
            As[c4 + 2][row] = va.z; As[c4 + 3][row] = va.w;
            float4 vb = *(const float4*)(Bm + (size_t)(n0 + row) * D_ + k0 + c4);
            Bs[c4 + 0][row] = vb.x; Bs[c4 + 1][row] = vb.y;
            Bs[c4 + 2][row] = vb.z; Bs[c4 + 3][row] = vb.w;
        }
        __syncthreads();
#pragma unroll
        for (int kk = 0; kk < 16; kk++) {
            float a[8], b[8];
#pragma unroll
            for (int i = 0; i < 8; i++) a[i] = As[kk][ty * 8 + i];
#pragma unroll
            for (int j = 0; j < 8; j++) b[j] = Bs[kk][tx * 8 + j];
#pragma unroll
            for (int i = 0; i < 8; i++)
#pragma unroll
                for (int j = 0; j < 8; j++) acc[i][j] += a[i] * b[j];
        }
        __syncthreads();
    }
    float prec = g_prec[0];
    int nb = n0 + tx * 8;
    float4 b2a = *(const float4*)(g_b2 + nb);
    float4 b2b = *(const float4*)(g_b2 + nb + 4);
#pragma unroll
    for (int i = 0; i < 8; i++) {
        int m = m0 + ty * 8 + i;
        float z2 = g_z2[m];
        float4 o1, o2;
        o1.x = (2.0f * acc[i][0] - z2 - b2a.x) * prec;
        o1.y = (2.0f * acc[i][1] - z2 - b2a.y) * prec;
        o1.z = (2.0f * acc[i][2] - z2 - b2a.z) * prec;
        o1.w = (2.0f * acc[i][3] - z2 - b2a.w) * prec;
        o2.x = (2.0f * acc[i][4] - z2 - b2b.x) * prec;
        o2.y = (2.0f * acc[i][5] - z2 - b2b.y) * prec;
        o2.z = (2.0f * acc[i][6] - z2 - b2b.z) * prec;
        o2.w = (2.0f * acc[i][7] - z2 - b2b.w) * prec;
        *(float4*)(g_scratch + (size_t)m * KS_ + nb)     = o1;
        *(float4*)(g_scratch + (size_t)m * KS_ + nb + 4) = o2;
    }
}

// ---------------- softmax / gumbel / W / prob / log_prob --------------------
__device__ __forceinline__ float block_reduce1(float a, float* red, int t, int is_sum) {
#pragma unroll
    for (int o = 16; o; o >>= 1) {
        float a2 = __shfl_xor_sync(0xffffffffu, a, o);
        a = is_sum ? (a + a2) : fmaxf(a, a2);
    }
    __syncthreads();
    if ((t & 31) == 0) red[t >> 5] = a;
    __syncthreads();
    float r = red[0];
#pragma unroll
    for (int w = 1; w < 8; w++) r = is_sum ? (r + red[w]) : fmaxf(r, red[w]);
    return r;
}

__global__ __launch_bounds__(256)
void k_soft(float* __restrict__ prob, float* __restrict__ logp,
            uint32_t k0, uint32_t k1) {
    __shared__ float red[8];
    int n = blockIdx.x;      // 0..1023
    int b = blockIdx.y;      // 0..15
    int t = threadIdx.x;
    size_t row = (size_t)b * N_ + n;

    float wla = 0.f, wlb = 0.f;

    for (int k = 0; k < K_; k++) {
        float cp = g_cprobs[b * K_ + k];
        size_t base = (row * K_ + k) * (size_t)S_;

        float la = g_scratch[base + t];
        float lb = g_scratch[base + t + 256];

        // partitionable gumbels: element flat index = base + s, counter (0, idx)
        uint32_t ia = (uint32_t)base + (uint32_t)t;
        float ga = gumbel_of(bits_to_unit(d_bits32(k0, k1, ia)));
        float gb = gumbel_of(bits_to_unit(d_bits32(k0, k1, ia + 256u)));
        float ya = (la + ga) * 2.0f;
        float yb = (lb + gb) * 2.0f;

        wla += cp * la; wlb += cp * lb;

        float M = block_reduce1(fmaxf(ya, yb), red, t, 0);
        float va = __expf(ya - M), vb = __expf(yb - M);
        float Z = block_reduce1(va + vb, red, t, 1);

        float f = cp / Z;
        g_scratch[base + t]       = va * f;
        g_scratch[base + t + 256] = vb * f;
    }

    // final softmax over weighted logits (S=512 per row)
    float M = block_reduce1(fmaxf(wla, wlb), red, t, 0);
    float ea = __expf(wla - M), eb = __expf(wlb - M);
    float Z = block_reduce1(ea + eb, red, t, 1);
    float lz = logf(Z);

    size_t p0 = row * S_;
    prob[p0 + t]       = ea / Z;
    prob[p0 + t + 256] = eb / Z;
    logp[p0 + t]       = (wla - M) - lz;
    logp[p0 + t + 256] = (wlb - M) - lz;
}

// ---------------- GEMM2: zq = W @ books -------------------------------------
__global__ __launch_bounds__(256)
void k_gemm2(const float* __restrict__ Bk, float* __restrict__ zq) {
    __shared__ float Ws[16][132];
    __shared__ float Bs[16][132];
    int t  = threadIdx.x;
    int m0 = blockIdx.y * 128, n0 = blockIdx.x * 128;
    int tx = t & 15, ty = t >> 4;
    float acc[8][8] = {};
    for (int kk0 = 0; kk0 < KS_; kk0 += 16) {
#pragma unroll
        for (int rep = 0; rep < 2; rep++) {
            int lin = rep * 256 + t;
            {
                int row = lin >> 2;
                int c4  = (lin & 3) << 2;
                float4 v = *(const float4*)(g_scratch + (size_t)(m0 + row) * KS_ + kk0 + c4);
                Ws[c4 + 0][row] = v.x; Ws[c4 + 1][row] = v.y;
                Ws[c4 + 2][row] = v.z; Ws[c4 + 3][row] = v.w;
            }
            {
                int row = lin >> 5;
                int c   = (lin & 31) << 2;
                *(float4*)(&Bs[row][c]) =
                    *(const float4*)(Bk + (size_t)(kk0 + row) * D_ + n0 + c);
            }
        }
        __syncthreads();
#pragma unroll
        for (int kk = 0; kk < 16; kk++) {
            float a[8], b[8];
#pragma unroll
            for (int i = 0; i < 8; i++) a[i] = Ws[kk][ty * 8 + i];
#pragma unroll
            for (int j = 0; j < 8; j++) b[j] = Bs[kk][tx * 8 + j];
#pragma unroll
            for (int i = 0; i < 8; i++)
#pragma unroll
                for (int j = 0; j < 8; j++) acc[i][j] += a[i] * b[j];
        }
        __syncthreads();
    }
#pragma unroll
    for (int i = 0; i < 8; i++) {
        int m = m0 + ty * 8 + i;
        float4 o1 = make_float4(acc[i][0], acc[i][1], acc[i][2], acc[i][3]);
        float4 o2 = make_float4(acc[i][4], acc[i][5], acc[i][6], acc[i][7]);
        *(float4*)(zq + (size_t)m * D_ + n0 + tx * 8)     = o1;
        *(float4*)(zq + (size_t)m * D_ + n0 + tx * 8 + 4) = o2;
    }
}

// ---------------- host-side threefry for key derivation ---------------------
static void h_tf(uint32_t k0, uint32_t k1, uint32_t x0, uint32_t x1,
                 uint32_t* o0, uint32_t* o1) {
    uint32_t ks2 = k0 ^ k1 ^ 0x1BD11BDAu;
    x0 += k0; x1 += k1;
    const int ra[4] = {13, 15, 26, 6}, rb[4] = {17, 29, 16, 24};
#define HR(r) { x0 += x1; x1 = (x1 << (r)) | (x1 >> (32 - (r))); x1 ^= x0; }
    for (int i = 0; i < 4; i++) HR(ra[i]); x0 += k1;  x1 += ks2 + 1u;
    for (int i = 0; i < 4; i++) HR(rb[i]); x0 += ks2; x1 += k0  + 2u;
    for (int i = 0; i < 4; i++) HR(ra[i]); x0 += k0;  x1 += k1  + 3u;
    for (int i = 0; i < 4; i++) HR(rb[i]); x0 += k1;  x1 += ks2 + 4u;
    for (int i = 0; i < 4; i++) HR(ra[i]); x0 += ks2; x1 += k0  + 5u;
#undef HR
    *o0 = x0; *o1 = x1;
}

extern "C" void kernel_launch(void* const* d_in, const int* in_sizes, int n_in,
                              void* d_out, int out_size) {
    const float* ze       = (const float*)d_in[0];
    const float* c_logits = (const float*)d_in[1];
    const float* books    = (const float*)d_in[2];
    const float* lpq      = (const float*)d_in[3];
    const float* lpqc     = (const float*)d_in[4];
    // d_in[5] = is_train (training path assumed)

    float* out     = (float*)d_out;
    float* zq      = out;                         // (B,N,D)
    float* pscalar = out + ZQ_SIZE;               // precision_q
    float* prob    = pscalar + 1;                 // (B,N,S)
    float* logp    = prob + PROB_SIZE;            // (B,N,S)

    // partitionable fold-like split of key(42): new_key[i] = tf(0,42, 0, i)
    uint32_t kg1_0, kg1_1, kg2_0, kg2_1;
    h_tf(0u, 42u, 0u, 0u, &kg1_0, &kg1_1);
    h_tf(0u, 42u, 0u, 1u, &kg2_0, &kg2_1);

    k_scalars<<<1, 1>>>(lpq, lpqc, pscalar);
    k_cprobs<<<1, 256>>>(c_logits, kg1_0, kg1_1);
    k_norms<<<96, 256>>>(ze, books);
    k_gemm1<<<dim3(KS_ / 128, M_TOT / 128), 256>>>(ze, books);
    k_soft<<<dim3(N_, B_), 256>>>(prob, logp, kg2_0, kg2_1);
    k_gemm2<<<dim3(D_ / 128, M_TOT / 128), 256>>>(books, zq);
}

// round 6
// speedup vs baseline: 1.2012x; 1.2012x over previous
#include <cuda_runtime.h>
#include <cstdint>
#include <cstddef>

#define B_    16
#define N_    1024
#define D_    256
#define K_    16
#define S_    512
#define M_TOT (B_*N_)          /* 16384 */
#define KS_   (K_*S_)          /* 8192  */
#define ZQ_SIZE   (M_TOT*D_)   /* 4194304 */
#define PROB_SIZE ((size_t)M_TOT*S_) /* 8388608 */

// ---------------- scratch ----------------------------------------------------
__device__ float g_scratch[(size_t)M_TOT * KS_];   // logit_all, then W in-place
__device__ float g_z2[M_TOT];
__device__ float g_b2[KS_];
__device__ float g_cprobs[B_ * K_];
__device__ float g_prec[2];

// ---------------- threefry2x32-20 (JAX partitionable) ------------------------
__device__ __forceinline__ void d_tf(uint32_t k0, uint32_t k1,
                                     uint32_t x0, uint32_t x1,
                                     uint32_t& o0, uint32_t& o1) {
    uint32_t ks2 = k0 ^ k1 ^ 0x1BD11BDAu;
    x0 += k0; x1 += k1;
#define TFR(r) { x0 += x1; x1 = __funnelshift_l(x1, x1, r); x1 ^= x0; }
    TFR(13) TFR(15) TFR(26) TFR(6)   x0 += k1;  x1 += ks2 + 1u;
    TFR(17) TFR(29) TFR(16) TFR(24)  x0 += ks2; x1 += k0  + 2u;
    TFR(13) TFR(15) TFR(26) TFR(6)   x0 += k0;  x1 += k1  + 3u;
    TFR(17) TFR(29) TFR(16) TFR(24)  x0 += k1;  x1 += ks2 + 4u;
    TFR(13) TFR(15) TFR(26) TFR(6)   x0 += ks2; x1 += k0  + 5u;
#undef TFR
    o0 = x0; o1 = x1;
}

__device__ __forceinline__ uint32_t d_bits32(uint32_t k0, uint32_t k1, uint32_t i) {
    uint32_t o0, o1;
    d_tf(k0, k1, 0u, i, o0, o1);
    return o0 ^ o1;                 // partitionable 32-bit extraction
}

__device__ __forceinline__ float bits_to_unit(uint32_t b) {
    return fmaxf(0.0f, __uint_as_float((b >> 9) | 0x3f800000u) - 1.0f);
}
__device__ __forceinline__ float gumbel_of(float u) {
    return -logf(-logf(u + 1e-10f) + 1e-10f);
}

// ---------------- tf32 helpers ------------------------------------------------
__device__ __forceinline__ uint32_t f2tf(float x) {
    uint32_t r;
    asm("cvt.rna.tf32.f32 %0, %1;" : "=r"(r) : "f"(x));
    return r;
}
__device__ __forceinline__ void split_tf(float x, uint32_t& hi, uint32_t& lo) {
    hi = f2tf(x);
    lo = f2tf(x - __uint_as_float(hi));
}
__device__ __forceinline__ void mma_tf32(float* c, const uint32_t* a, const uint32_t* b) {
    asm volatile(
        "mma.sync.aligned.m16n8k8.row.col.f32.tf32.tf32.f32 "
        "{%0,%1,%2,%3}, {%4,%5,%6,%7}, {%8,%9}, {%0,%1,%2,%3};"
        : "+f"(c[0]), "+f"(c[1]), "+f"(c[2]), "+f"(c[3])
        : "r"(a[0]), "r"(a[1]), "r"(a[2]), "r"(a[3]), "r"(b[0]), "r"(b[1]));
}

__device__ __forceinline__ void cp16(void* smem, const void* gmem) {
    unsigned s = (unsigned)__cvta_generic_to_shared(smem);
    asm volatile("cp.async.cg.shared.global [%0], [%1], 16;" :: "r"(s), "l"(gmem));
}
#define CP_COMMIT asm volatile("cp.async.commit_group;")
#define CP_WAIT1  asm volatile("cp.async.wait_group 1;")
#define CP_WAIT0  asm volatile("cp.async.wait_group 0;")

// ---------------- tiny kernels ------------------------------------------------
__global__ void k_scalars(const float* __restrict__ lpq,
                          const float* __restrict__ lpqc,
                          float* __restrict__ out_scalar) {
    float pq   = 1.0f + expf(lpq[0]);
    float prec = 0.5f / fmaxf(pq, 1e-10f);
    float pqc  = 1.0f + expf(lpqc[0]);
    float precc= 0.5f / fmaxf(pqc, 1e-10f);
    g_prec[0] = prec;
    g_prec[1] = precc;
    out_scalar[0] = prec;
}

__global__ void k_cprobs(const float* __restrict__ c_logits,
                         uint32_t k0, uint32_t k1) {
    __shared__ float lg[256];
    int t = threadIdx.x;
    float u = bits_to_unit(d_bits32(k0, k1, (uint32_t)t));
    float pqc = g_prec[1];
    lg[t] = (c_logits[t] * pqc + gumbel_of(u)) * 2.0f;
    __syncthreads();
    if (t < 16) {
        float mx = -1e30f;
        for (int j = 0; j < 16; j++) mx = fmaxf(mx, lg[t * 16 + j]);
        float e[16], sm = 0.0f;
        for (int j = 0; j < 16; j++) { e[j] = expf(lg[t * 16 + j] - mx); sm += e[j]; }
        for (int j = 0; j < 16; j++) g_cprobs[t * 16 + j] = e[j] / sm;
    }
}

__global__ void k_norms(const float* __restrict__ ze,
                        const float* __restrict__ books) {
    int warps = (gridDim.x * blockDim.x) >> 5;
    int w     = (blockIdx.x * blockDim.x + threadIdx.x) >> 5;
    int lane  = threadIdx.x & 31;
    for (int r = w; r < M_TOT + KS_; r += warps) {
        const float4* p = (r < M_TOT)
            ? (const float4*)(ze + (size_t)r * D_)
            : (const float4*)(books + (size_t)(r - M_TOT) * D_);
        float s = 0.0f;
#pragma unroll
        for (int j = 0; j < 2; j++) {
            float4 v = p[lane + j * 32];
            s += v.x * v.x + v.y * v.y + v.z * v.z + v.w * v.w;
        }
#pragma unroll
        for (int o = 16; o; o >>= 1) s += __shfl_xor_sync(0xffffffffu, s, o);
        if (lane == 0) { if (r < M_TOT) g_z2[r] = s; else g_b2[r - M_TOT] = s; }
    }
}

// ============ GEMM1 (tensor core): scratch = (2*ze.booksT - z2 - b2)*prec ====
// A = ze [M,256] k-contig; B = books [KS,256] k-contig. C tile 128x128, BK=16.
#define PA 20
#define PB 20
__global__ __launch_bounds__(256)
void k_gemm1_tc(const float* __restrict__ A, const float* __restrict__ Bm) {
    __shared__ float As[2][128 * PA];
    __shared__ float Bs[2][128 * PB];
    const int t = threadIdx.x;
    const int m0 = blockIdx.y * 128, n0 = blockIdx.x * 128;
    const int wid = t >> 5, lane = t & 31;
    const int wm = wid & 1, wn = wid >> 1;          // 2 x 4 warp grid
    const int gr = lane >> 2, ct = lane & 3;

    float acc[4][4][4] = {};

    auto issue = [&](int kt, int st) {
#pragma unroll
        for (int i = 0; i < 2; i++) {
            int c   = t + i * 256;
            int row = c >> 2;
            int kk  = (c & 3) << 2;
            cp16(&As[st][row * PA + kk], A  + (size_t)(m0 + row) * D_ + kt * 16 + kk);
            cp16(&Bs[st][row * PB + kk], Bm + (size_t)(n0 + row) * D_ + kt * 16 + kk);
        }
        CP_COMMIT;
    };

    const int T = D_ / 16;        // 16
    issue(0, 0);
    issue(1, 1);
    for (int kt = 0; kt < T; kt++) {
        if (kt + 1 < T) { CP_WAIT1; } else { CP_WAIT0; }
        __syncthreads();
        const int st = kt & 1;
#pragma unroll
        for (int k8 = 0; k8 < 2; k8++) {
            const int kb = k8 * 8;
            uint32_t ah[4][4], al[4][4], bh[4][2], bl[4][2];
#pragma unroll
            for (int f = 0; f < 4; f++) {
                int r = wm * 64 + f * 16 + gr;
                split_tf(As[st][r * PA + kb + ct],           ah[f][0], al[f][0]);
                split_tf(As[st][(r + 8) * PA + kb + ct],     ah[f][1], al[f][1]);
                split_tf(As[st][r * PA + kb + ct + 4],       ah[f][2], al[f][2]);
                split_tf(As[st][(r + 8) * PA + kb + ct + 4], ah[f][3], al[f][3]);
            }
#pragma unroll
            for (int j = 0; j < 4; j++) {
                int n = wn * 32 + j * 8 + gr;
                split_tf(Bs[st][n * PB + kb + ct],     bh[j][0], bl[j][0]);
                split_tf(Bs[st][n * PB + kb + ct + 4], bh[j][1], bl[j][1]);
            }
#pragma unroll
            for (int f = 0; f < 4; f++)
#pragma unroll
                for (int j = 0; j < 4; j++) {
                    mma_tf32(acc[f][j], ah[f], bh[j]);
                    mma_tf32(acc[f][j], ah[f], bl[j]);
                    mma_tf32(acc[f][j], al[f], bh[j]);
                }
        }
        __syncthreads();
        if (kt + 2 < T) issue(kt + 2, st);
    }

    const float prec = g_prec[0];
#pragma unroll
    for (int f = 0; f < 4; f++) {
        int m = m0 + wm * 64 + f * 16 + gr;
        float z2a = g_z2[m], z2b = g_z2[m + 8];
#pragma unroll
        for (int j = 0; j < 4; j++) {
            int n = n0 + wn * 32 + j * 8 + ct * 2;
            float b2x = g_b2[n], b2y = g_b2[n + 1];
            float2 v0, v1;
            v0.x = (2.0f * acc[f][j][0] - z2a - b2x) * prec;
            v0.y = (2.0f * acc[f][j][1] - z2a - b2y) * prec;
            v1.x = (2.0f * acc[f][j][2] - z2b - b2x) * prec;
            v1.y = (2.0f * acc[f][j][3] - z2b - b2y) * prec;
            *(float2*)(g_scratch + (size_t)m * KS_ + n)       = v0;
            *(float2*)(g_scratch + (size_t)(m + 8) * KS_ + n) = v1;
        }
    }
}

// ============ GEMM2 (tensor core): zq = W @ books ============================
// A = g_scratch [M, 8192] k-contig; B = books as [8192, 256] n-contig.
#define PB2 132
__global__ __launch_bounds__(256)
void k_gemm2_tc(const float* __restrict__ Bk, float* __restrict__ zq) {
    __shared__ float As[2][128 * PA];
    __shared__ float Bs2[2][16 * PB2];
    const int t = threadIdx.x;
    const int m0 = blockIdx.y * 128, n0 = blockIdx.x * 128;
    const int wid = t >> 5, lane = t & 31;
    const int wm = wid & 1, wn = wid >> 1;
    const int gr = lane >> 2, ct = lane & 3;

    float acc[4][4][4] = {};

    auto issue = [&](int kt, int st) {
#pragma unroll
        for (int i = 0; i < 2; i++) {
            int c   = t + i * 256;
            int rowA = c >> 2;
            int kkA  = (c & 3) << 2;
            cp16(&As[st][rowA * PA + kkA],
                 g_scratch + (size_t)(m0 + rowA) * KS_ + kt * 16 + kkA);
            int rowB = c >> 5;
            int nn   = (c & 31) << 2;
            cp16(&Bs2[st][rowB * PB2 + nn],
                 Bk + (size_t)(kt * 16 + rowB) * D_ + n0 + nn);
        }
        CP_COMMIT;
    };

    const int T = KS_ / 16;       // 512
    issue(0, 0);
    issue(1, 1);
    for (int kt = 0; kt < T; kt++) {
        if (kt + 1 < T) { CP_WAIT1; } else { CP_WAIT0; }
        __syncthreads();
        const int st = kt & 1;
#pragma unroll
        for (int k8 = 0; k8 < 2; k8++) {
            const int kb = k8 * 8;
            uint32_t ah[4][4], al[4][4], bh[4][2], bl[4][2];
#pragma unroll
            for (int f = 0; f < 4; f++) {
                int r = wm * 64 + f * 16 + gr;
                split_tf(As[st][r * PA + kb + ct],           ah[f][0], al[f][0]);
                split_tf(As[st][(r + 8) * PA + kb + ct],     ah[f][1], al[f][1]);
                split_tf(As[st][r * PA + kb + ct + 4],       ah[f][2], al[f][2]);
                split_tf(As[st][(r + 8) * PA + kb + ct + 4], ah[f][3], al[f][3]);
            }
#pragma unroll
            for (int j = 0; j < 4; j++) {
                int n = wn * 32 + j * 8 + gr;
                split_tf(Bs2[st][(kb + ct) * PB2 + n],     bh[j][0], bl[j][0]);
                split_tf(Bs2[st][(kb + ct + 4) * PB2 + n], bh[j][1], bl[j][1]);
            }
#pragma unroll
            for (int f = 0; f < 4; f++)
#pragma unroll
                for (int j = 0; j < 4; j++) {
                    mma_tf32(acc[f][j], ah[f], bh[j]);
                    mma_tf32(acc[f][j], ah[f], bl[j]);
                    mma_tf32(acc[f][j], al[f], bh[j]);
                }
        }
        __syncthreads();
        if (kt + 2 < T) issue(kt + 2, st);
    }

#pragma unroll
    for (int f = 0; f < 4; f++) {
        int m = m0 + wm * 64 + f * 16 + gr;
#pragma unroll
        for (int j = 0; j < 4; j++) {
            int n = n0 + wn * 32 + j * 8 + ct * 2;
            *(float2*)(zq + (size_t)m * D_ + n)       = make_float2(acc[f][j][0], acc[f][j][1]);
            *(float2*)(zq + (size_t)(m + 8) * D_ + n) = make_float2(acc[f][j][2], acc[f][j][3]);
        }
    }
}

// ---------------- softmax / gumbel / W / prob / log_prob ---------------------
__device__ __forceinline__ float block_reduce1(float a, float* red, int t, int is_sum) {
#pragma unroll
    for (int o = 16; o; o >>= 1) {
        float a2 = __shfl_xor_sync(0xffffffffu, a, o);
        a = is_sum ? (a + a2) : fmaxf(a, a2);
    }
    __syncthreads();
    if ((t & 31) == 0) red[t >> 5] = a;
    __syncthreads();
    float r = red[0];
#pragma unroll
    for (int w = 1; w < 8; w++) r = is_sum ? (r + red[w]) : fmaxf(r, red[w]);
    return r;
}

__global__ __launch_bounds__(256)
void k_soft(float* __restrict__ prob, float* __restrict__ logp,
            uint32_t k0, uint32_t k1) {
    __shared__ float red[8];
    int n = blockIdx.x;
    int b = blockIdx.y;
    int t = threadIdx.x;
    size_t row = (size_t)b * N_ + n;

    float wla = 0.f, wlb = 0.f;

    for (int k = 0; k < K_; k++) {
        float cp = g_cprobs[b * K_ + k];
        size_t base = (row * K_ + k) * (size_t)S_;

        float la = g_scratch[base + t];
        float lb = g_scratch[base + t + 256];

        uint32_t ia = (uint32_t)base + (uint32_t)t;
        float ga = gumbel_of(bits_to_unit(d_bits32(k0, k1, ia)));
        float gb = gumbel_of(bits_to_unit(d_bits32(k0, k1, ia + 256u)));
        float ya = (la + ga) * 2.0f;
        float yb = (lb + gb) * 2.0f;

        wla += cp * la; wlb += cp * lb;

        float M = block_reduce1(fmaxf(ya, yb), red, t, 0);
        float va = __expf(ya - M), vb = __expf(yb - M);
        float Z = block_reduce1(va + vb, red, t, 1);

        float f = cp / Z;
        g_scratch[base + t]       = va * f;
        g_scratch[base + t + 256] = vb * f;
    }

    float M = block_reduce1(fmaxf(wla, wlb), red, t, 0);
    float ea = __expf(wla - M), eb = __expf(wlb - M);
    float Z = block_reduce1(ea + eb, red, t, 1);
    float lz = logf(Z);

    size_t p0 = row * S_;
    prob[p0 + t]       = ea / Z;
    prob[p0 + t + 256] = eb / Z;
    logp[p0 + t]       = (wla - M) - lz;
    logp[p0 + t + 256] = (wlb - M) - lz;
}

// ---------------- host-side threefry ------------------------------------------
static void h_tf(uint32_t k0, uint32_t k1, uint32_t x0, uint32_t x1,
                 uint32_t* o0, uint32_t* o1) {
    uint32_t ks2 = k0 ^ k1 ^ 0x1BD11BDAu;
    x0 += k0; x1 += k1;
    const int ra[4] = {13, 15, 26, 6}, rb[4] = {17, 29, 16, 24};
#define HR(r) { x0 += x1; x1 = (x1 << (r)) | (x1 >> (32 - (r))); x1 ^= x0; }
    for (int i = 0; i < 4; i++) HR(ra[i]); x0 += k1;  x1 += ks2 + 1u;
    for (int i = 0; i < 4; i++) HR(rb[i]); x0 += ks2; x1 += k0  + 2u;
    for (int i = 0; i < 4; i++) HR(ra[i]); x0 += k0;  x1 += k1  + 3u;
    for (int i = 0; i < 4; i++) HR(rb[i]); x0 += k1;  x1 += ks2 + 4u;
    for (int i = 0; i < 4; i++) HR(ra[i]); x0 += ks2; x1 += k0  + 5u;
#undef HR
    *o0 = x0; *o1 = x1;
}

extern "C" void kernel_launch(void* const* d_in, const int* in_sizes, int n_in,
                              void* d_out, int out_size) {
    const float* ze       = (const float*)d_in[0];
    const float* c_logits = (const float*)d_in[1];
    const float* books    = (const float*)d_in[2];
    const float* lpq      = (const float*)d_in[3];
    const float* lpqc     = (const float*)d_in[4];

    float* out     = (float*)d_out;
    float* zq      = out;
    float* pscalar = out + ZQ_SIZE;
    float* prob    = pscalar + 1;
    float* logp    = prob + PROB_SIZE;

    uint32_t kg1_0, kg1_1, kg2_0, kg2_1;
    h_tf(0u, 42u, 0u, 0u, &kg1_0, &kg1_1);
    h_tf(0u, 42u, 0u, 1u, &kg2_0, &kg2_1);

    k_scalars<<<1, 1>>>(lpq, lpqc, pscalar);
    k_cprobs<<<1, 256>>>(c_logits, kg1_0, kg1_1);
    k_norms<<<96, 256>>>(ze, books);
    k_gemm1_tc<<<dim3(KS_ / 128, M_TOT / 128), 256>>>(ze, books);
    k_soft<<<dim3(N_, B_), 256>>>(prob, logp, kg2_0, kg2_1);
    k_gemm2_tc<<<dim3(D_ / 128, M_TOT / 128), 256>>>(books, zq);
}